// round 16
// baseline (speedup 1.0000x reference)
#include <cuda_runtime.h>
#include <math.h>

// SPECULATIVE SINGLE-PASS block quantize, split into 3 launches (persistent
// spin-barrier kernels measured a ~15us steady-state harness penalty vs ~5us
// for split launches; launch boundaries are the cheaper grid sync here).
//   K1: decimated sample (every 32nd stripe) -> g_samp partials       (~4us)
//   K2: prologue-reduce g_samp -> e_spec; ONE stream: read x, track true
//       max, quantize with e_spec, write y; g_full partials          (~163us)
//       => 1.0 GB DRAM traffic instead of 1.5 GB
//   K3: reduce both partials; if exp(e_glob) != exp(e_spec) (never for this
//       data, uniform + replay-deterministic), requantize with e_glob (~3us)
// Sample max <= global max always, so speculation only undershoots and the
// undershoot is always detected. Partials are write-always -> no reset pass.
#define NCTA 2368          // 148 SMs * 16 CTAs (best-measured streaming grid)
#define THREADS 256
#define DECIM 32           // sample every 32nd stripe (~16 MB, coalesced)

__device__ float g_samp[NCTA];
__device__ float g_full[NCTA];

__device__ __forceinline__ float warp_max(float m) {
    #pragma unroll
    for (int o = 16; o > 0; o >>= 1)
        m = fmaxf(m, __shfl_xor_sync(0xffffffffu, m, o));
    return m;
}

__device__ __forceinline__ float block_reduce_max(float m) {
    __shared__ float sm[THREADS / 32];
    m = warp_max(m);
    int lane = threadIdx.x & 31;
    int w = threadIdx.x >> 5;
    if (lane == 0) sm[w] = m;
    __syncthreads();
    if (w == 0) {
        m = (lane < (THREADS / 32)) ? sm[lane] : 0.0f;
        m = warp_max(m);
    }
    return m;  // valid in warp 0
}

__device__ __forceinline__ float max4(float4 v) {
    return fmaxf(fmaxf(fabsf(v.x), fabsf(v.y)), fmaxf(fabsf(v.z), fabsf(v.w)));
}

__device__ __forceinline__ float bq_quant_one(float v, float s, float inv_s) {
    v = (v >= 0.0f) ? fmaxf(v, 1e-10f) : fminf(v, -1e-10f);  // zeros -> +1e-10
    float i = rintf(v * s);                                   // half-to-even
    i = fminf(fmaxf(i, -128.0f), 127.0f);                     // clip to int8 range
    return i * inv_s;                                         // exact pow2 scale
}

__device__ __forceinline__ float4 quant4(float4 v, float s, float inv_s) {
    v.x = bq_quant_one(v.x, s, inv_s);
    v.y = bq_quant_one(v.y, s, inv_s);
    v.z = bq_quant_one(v.z, s, inv_s);
    v.w = bq_quant_one(v.w, s, inv_s);
    return v;
}

// clipped exponent from a raw max
__device__ __forceinline__ float exp_from_max(float m) {
    float maxv = fmaxf(m, 1e-10f);  // 1e-10 clamp can only raise tiny maxima
    return fminf(fmaxf(floorf(log2f(maxv)), -128.0f), 127.0f);
}

// reduce an NCTA partials array across the CTA (arrays are L2-resident)
__device__ __forceinline__ float reduce_partials(const float* arr) {
    float m = 0.0f;
    for (unsigned p = threadIdx.x; p < NCTA; p += THREADS)
        m = fmaxf(m, __ldcg(&arr[p]));
    return block_reduce_max(m);  // valid in warp 0
}

// ---- K1: decimated sample max ----
__global__ void __launch_bounds__(THREADS)
bq_sample_kernel(const float4* __restrict__ x, unsigned nvec,
                 const float* __restrict__ xs, unsigned ntail_base, unsigned ntail) {
    const unsigned stride = NCTA * THREADS;
    float m = 0.0f;
    for (unsigned i = blockIdx.x * THREADS + threadIdx.x; i < nvec; i += stride * DECIM)
        m = fmaxf(m, max4(x[i]));
    if (blockIdx.x == 0 && threadIdx.x < ntail)
        m = fmaxf(m, fabsf(xs[ntail_base + threadIdx.x]));   // tail in sample: exact coverage
    m = block_reduce_max(m);
    if (threadIdx.x == 0)
        g_samp[blockIdx.x] = m;
}

// ---- K2: speculative fused stream (read once; track true max) ----
__global__ void __launch_bounds__(THREADS)
bq_specq_kernel(const float4* __restrict__ x, float4* __restrict__ y,
                unsigned nvec,
                const float* __restrict__ xs, float* __restrict__ ys,
                unsigned ntail_base, unsigned ntail) {
    __shared__ float s_sc[2];
    {
        float mm = reduce_partials(g_samp);
        if (threadIdx.x == 0) {
            float e = exp_from_max(mm);
            s_sc[0] = exp2f(6.0f - e);      // 2^(-e + (bits-2)), bits=8
            s_sc[1] = exp2f(e - 6.0f);
        }
    }
    __syncthreads();
    const float s = s_sc[0], inv_s = s_sc[1];

    const unsigned stride = NCTA * THREADS;
    float m = 0.0f;
    for (unsigned i = blockIdx.x * THREADS + threadIdx.x; i < nvec; i += stride) {
        float4 v = x[i];
        m = fmaxf(m, max4(v));
        y[i] = quant4(v, s, inv_s);
    }
    if (blockIdx.x == 0 && threadIdx.x < ntail) {
        float vt = xs[ntail_base + threadIdx.x];
        m = fmaxf(m, fabsf(vt));
        ys[ntail_base + threadIdx.x] = bq_quant_one(vt, s, inv_s);
    }

    m = block_reduce_max(m);
    if (threadIdx.x == 0)
        g_full[blockIdx.x] = m;
}

// ---- K3: verify speculation; requantize only on exponent mismatch ----
__global__ void __launch_bounds__(THREADS)
bq_check_kernel(const float4* __restrict__ x, float4* __restrict__ y,
                unsigned nvec,
                const float* __restrict__ xs, float* __restrict__ ys,
                unsigned ntail_base, unsigned ntail) {
    __shared__ float s_info[3];   // e_spec, e_glob (scales derived if needed)
    {
        float ms = reduce_partials(g_samp);
        float mf = reduce_partials(g_full);
        if (threadIdx.x == 0) {
            s_info[0] = exp_from_max(ms);
            s_info[1] = exp_from_max(fmaxf(ms, mf));  // global includes sample by def.
        }
    }
    __syncthreads();
    const float e_spec = s_info[0], e_glob = s_info[1];
    if (e_glob == e_spec) return;   // uniform, deterministic -> whole grid exits

    const float s  = exp2f(6.0f - e_glob);
    const float iv = exp2f(e_glob - 6.0f);
    const unsigned stride = NCTA * THREADS;
    for (unsigned i = blockIdx.x * THREADS + threadIdx.x; i < nvec; i += stride)
        y[i] = quant4(x[i], s, iv);
    if (blockIdx.x == 0 && threadIdx.x < ntail)
        ys[ntail_base + threadIdx.x] =
            bq_quant_one(xs[ntail_base + threadIdx.x], s, iv);
}

extern "C" void kernel_launch(void* const* d_in, const int* in_sizes, int n_in,
                              void* d_out, int out_size) {
    const float* x = (const float*)d_in[0];
    float* y = (float*)d_out;
    unsigned n = (unsigned)in_sizes[0];
    unsigned nvec = n >> 2;
    unsigned ntail_base = nvec << 2;
    unsigned ntail = n - ntail_base;

    bq_sample_kernel<<<NCTA, THREADS>>>(
        (const float4*)x, nvec, x, ntail_base, ntail);
    bq_specq_kernel<<<NCTA, THREADS>>>(
        (const float4*)x, (float4*)y, nvec, x, y, ntail_base, ntail);
    bq_check_kernel<<<NCTA, THREADS>>>(
        (const float4*)x, (float4*)y, nvec, x, y, ntail_base, ntail);
}

// round 17
// speedup vs baseline: 1.0192x; 1.0192x over previous
#include <cuda_runtime.h>
#include <math.h>

// SPECULATIVE SINGLE-PASS block quantize (fused persistent form — measured
// faster than the 3-launch split: 184.8 vs 188.4 us).
//   phase 0: decimated sample (every 128th float8 stripe, ~4MB) -> e_spec
//   phase 1: ONE stream: read x once (256-bit), track true max, quantize with
//            e_spec, write y (256-bit)  => 1.0 GB DRAM traffic, not 1.5 GB
//   phase 2: if e_glob != e_spec (P ~ e^-500 for this data; uniform +
//            replay-deterministic), requantize in place -- always correct.
// Grid = one wave (148 SMs x 8 CTAs, launch_bounds(256,8) caps regs at 32 so
// co-residency is guaranteed); ticket barrier cannot deadlock; counter only
// grows -> graph-replay-safe.
#define NCTA 1184
#define THREADS 256
#define DECIM 128

__device__ float g_samp[NCTA];
__device__ float g_full[NCTA];
__device__ unsigned g_ticket;   // zero-init; grows monotonically across replays

__device__ __forceinline__ float warp_max(float m) {
    #pragma unroll
    for (int o = 16; o > 0; o >>= 1)
        m = fmaxf(m, __shfl_xor_sync(0xffffffffu, m, o));
    return m;
}

__device__ __forceinline__ float block_reduce_max(float m) {
    __shared__ float sm[THREADS / 32];
    m = warp_max(m);
    int lane = threadIdx.x & 31;
    int w = threadIdx.x >> 5;
    if (lane == 0) sm[w] = m;
    __syncthreads();
    if (w == 0) {
        m = (lane < (THREADS / 32)) ? sm[lane] : 0.0f;
        m = warp_max(m);
    }
    return m;  // valid in warp 0
}

// 256-bit global load/store (sm_103a supports v8.b32)
__device__ __forceinline__ void ld8(const float* p, float4& a, float4& b) {
    unsigned r0, r1, r2, r3, r4, r5, r6, r7;
    asm volatile("ld.global.v8.b32 {%0,%1,%2,%3,%4,%5,%6,%7}, [%8];"
                 : "=r"(r0), "=r"(r1), "=r"(r2), "=r"(r3),
                   "=r"(r4), "=r"(r5), "=r"(r6), "=r"(r7) : "l"(p));
    a.x = __uint_as_float(r0); a.y = __uint_as_float(r1);
    a.z = __uint_as_float(r2); a.w = __uint_as_float(r3);
    b.x = __uint_as_float(r4); b.y = __uint_as_float(r5);
    b.z = __uint_as_float(r6); b.w = __uint_as_float(r7);
}
__device__ __forceinline__ void st8(float* p, float4 a, float4 b) {
    asm volatile("st.global.v8.b32 [%0], {%1,%2,%3,%4,%5,%6,%7,%8};"
                 :: "l"(p),
                    "r"(__float_as_uint(a.x)), "r"(__float_as_uint(a.y)),
                    "r"(__float_as_uint(a.z)), "r"(__float_as_uint(a.w)),
                    "r"(__float_as_uint(b.x)), "r"(__float_as_uint(b.y)),
                    "r"(__float_as_uint(b.z)), "r"(__float_as_uint(b.w))
                 : "memory");
}

__device__ __forceinline__ float max4(float4 v) {
    return fmaxf(fmaxf(fabsf(v.x), fabsf(v.y)), fmaxf(fabsf(v.z), fabsf(v.w)));
}

__device__ __forceinline__ float bq_quant_one(float v, float s, float inv_s) {
    v = (v >= 0.0f) ? fmaxf(v, 1e-10f) : fminf(v, -1e-10f);  // zeros -> +1e-10
    float i = rintf(v * s);                                   // half-to-even
    i = fminf(fmaxf(i, -128.0f), 127.0f);                     // clip to int8 range
    return i * inv_s;                                         // exact pow2 scale
}

__device__ __forceinline__ float4 quant4(float4 v, float s, float inv_s) {
    v.x = bq_quant_one(v.x, s, inv_s);
    v.y = bq_quant_one(v.y, s, inv_s);
    v.z = bq_quant_one(v.z, s, inv_s);
    v.w = bq_quant_one(v.w, s, inv_s);
    return v;
}

__device__ __forceinline__ void grid_barrier_t0() {
    if (threadIdx.x == 0) {
        __threadfence();                      // release prior global writes
        unsigned t = atomicAdd(&g_ticket, 1u);
        unsigned target = (t / NCTA + 1u) * NCTA;
        for (;;) {
            unsigned cur;
            asm volatile("ld.global.acquire.gpu.u32 %0, [%1];"
                         : "=r"(cur) : "l"(&g_ticket));
            if (cur >= target) break;
            __nanosleep(64);
        }
    }
    __syncthreads();
}

__device__ __forceinline__ float exp_from_max(float m) {
    float maxv = fmaxf(m, 1e-10f);  // 1e-10 clamp can only raise tiny maxima
    return fminf(fmaxf(floorf(log2f(maxv)), -128.0f), 127.0f);
}

__global__ void __launch_bounds__(THREADS, 8)
bq_spec_kernel(const float* __restrict__ x, float* __restrict__ y,
               unsigned nvec8,
               const float* __restrict__ xs, float* __restrict__ ys,
               unsigned ntail_base, unsigned ntail) {
    __shared__ float sh_b;

    const unsigned stride = NCTA * THREADS;                 // in float8 units
    const unsigned t0 = blockIdx.x * THREADS + threadIdx.x;

    // ---- phase 0: decimated sample (~4MB, coalesced 1024B/warp) ----
    float ms = 0.0f;
    for (unsigned i = t0; i < nvec8; i += stride * DECIM) {
        float4 a, b;
        ld8(x + (size_t)i * 8u, a, b);
        ms = fmaxf(ms, fmaxf(max4(a), max4(b)));
    }
    ms = block_reduce_max(ms);
    if (threadIdx.x == 0) g_samp[blockIdx.x] = ms;
    grid_barrier_t0();

    {
        float mm = 0.0f;
        for (unsigned p = threadIdx.x; p < NCTA; p += THREADS)
            mm = fmaxf(mm, __ldcg(&g_samp[p]));
        mm = block_reduce_max(mm);
        if (threadIdx.x == 0) sh_b = mm;
        __syncthreads();
    }
    const float e_spec = exp_from_max(sh_b);
    const float s_spec  = exp2f(6.0f - e_spec);   // 2^(-e + (bits-2)), bits=8
    const float iv_spec = exp2f(e_spec - 6.0f);

    // ---- phase 1: single fused 256-bit stream ----
    float m = 0.0f;
    for (unsigned i = t0; i < nvec8; i += stride) {
        float4 a, b;
        ld8(x + (size_t)i * 8u, a, b);
        m = fmaxf(m, fmaxf(max4(a), max4(b)));
        st8(y + (size_t)i * 8u,
            quant4(a, s_spec, iv_spec), quant4(b, s_spec, iv_spec));
    }
    if (blockIdx.x == 0 && threadIdx.x < ntail) {
        float vt = xs[ntail_base + threadIdx.x];
        m = fmaxf(m, fabsf(vt));
        ys[ntail_base + threadIdx.x] = bq_quant_one(vt, s_spec, iv_spec);
    }

    m = block_reduce_max(m);
    if (threadIdx.x == 0) g_full[blockIdx.x] = m;
    grid_barrier_t0();

    {
        float mm = 0.0f;
        for (unsigned p = threadIdx.x; p < NCTA; p += THREADS)
            mm = fmaxf(mm, __ldcg(&g_full[p]));
        mm = block_reduce_max(mm);
        if (threadIdx.x == 0) sh_b = mm;
        __syncthreads();
    }
    const float e_glob = exp_from_max(sh_b);

    // ---- phase 2: fixup (uniform branch; same thread -> same elements) ----
    if (e_glob != e_spec) {
        const float s_g  = exp2f(6.0f - e_glob);
        const float iv_g = exp2f(e_glob - 6.0f);
        for (unsigned i = t0; i < nvec8; i += stride) {
            float4 a, b;
            ld8(x + (size_t)i * 8u, a, b);
            st8(y + (size_t)i * 8u, quant4(a, s_g, iv_g), quant4(b, s_g, iv_g));
        }
        if (blockIdx.x == 0 && threadIdx.x < ntail)
            ys[ntail_base + threadIdx.x] =
                bq_quant_one(xs[ntail_base + threadIdx.x], s_g, iv_g);
    }
}

extern "C" void kernel_launch(void* const* d_in, const int* in_sizes, int n_in,
                              void* d_out, int out_size) {
    const float* x = (const float*)d_in[0];
    float* y = (float*)d_out;
    unsigned n = (unsigned)in_sizes[0];
    unsigned nvec8 = n >> 3;                 // full float8 (32B) vectors
    unsigned ntail_base = nvec8 << 3;
    unsigned ntail = n - ntail_base;         // up to 7 scalars

    bq_spec_kernel<<<NCTA, THREADS>>>(
        x, y, nvec8, x, y, ntail_base, ntail);
}